// round 7
// baseline (speedup 1.0000x reference)
#include <cuda_runtime.h>

// crossMSEloss: B=4, S=256, P=64, D=63
// out[b,s] = sum_p conf[p] * min_q ||pred_p - tgt_q||
//          + sum_q min_p ( ||pred_p - tgt_q|| / conf[p] )
//
// GEMM-form (norm trick), f32x2 FMA mainloop, 4p x 4q tiles, XOR-swizzled
// transposed targets. Front end: 8 batched LDG.128/thread (single latency
// exposure), STS.128 pred stores, per-component swizzled target scatter,
// norms computed from smem (no shuffle chains before the mainloop).

#define NP 64
#define SP_S 68     // preds stride: 272B, float4-aligned, conflict-free
#define CM_S 68

typedef unsigned long long u64;

__device__ __forceinline__ void ffma2(u64& d, u64 a, u64 b) {
    asm("fma.rn.f32x2 %0, %1, %2, %0;" : "+l"(d) : "l"(a), "l"(b));
}
__device__ __forceinline__ void unpack2(float& lo, float& hi, u64 v) {
    asm("mov.b64 {%0, %1}, %2;" : "=f"(lo), "=f"(hi) : "l"(v));
}

// st_t physical float offset for logical (d, q):
// row d = 64 floats (256B); 16B chunk (q>>2) ^ (d&15); element (q&3).
__device__ __forceinline__ int stoff(int d, int q) {
    return d * 64 + (((q >> 2) ^ (d & 15)) << 2) + (q & 3);
}

__global__ __launch_bounds__(256, 4)
void cross_mse_loss_kernel(const float* __restrict__ inp,
                           const float* __restrict__ tgt,
                           float* __restrict__ out)
{
    __shared__ __align__(16) float sp[NP * SP_S];   // preds [p][d], d=63 -> 0
    __shared__ __align__(16) float st_t[NP * 64];   // targets [d][swizzled q]
    __shared__ float cm[8 * CM_S];
    __shared__ float rm[NP];
    __shared__ float conf[NP];
    __shared__ float cinv2[NP];
    __shared__ float pn[NP];
    __shared__ float qn[NP];
    __shared__ float red[128];

    const int bs   = blockIdx.x;
    const int tid  = threadIdx.x;
    const int lane15 = tid & 15;

    const float* ip = inp + (size_t)bs * (NP * 64);
    const float* tp = tgt + (size_t)bs * (NP * 63);

    // ================= Front end: batched loads =================
    const float4* ip4 = (const float4*)ip;
    const float4* tp4 = (const float4*)tp;   // 1008 float4

    float4 pv[4];
    #pragma unroll
    for (int r = 0; r < 4; r++) pv[r] = ip4[tid + r * 256];

    float4 tv[4];
    int tidx[4];
    #pragma unroll
    for (int r = 0; r < 4; r++) {
        int idx = tid + r * 256;
        tidx[r] = idx;
        tv[r] = (idx < 1008) ? tp4[idx] : make_float4(0.f, 0.f, 0.f, 0.f);
    }

    // ---- Pred stores: one STS.128 per r; conf handled on the d4==60 lane ----
    #pragma unroll
    for (int r = 0; r < 4; r++) {
        int idx = tid + r * 256;
        int p   = idx >> 4;
        int d4  = lane15 << 2;
        float4 v = pv[r];
        if (d4 == 60) {
            conf[p] = v.w;
            float ci = 1.0f / v.w;
            cinv2[p] = ci * ci;
            v.w = 0.0f;
        }
        *(float4*)(sp + p * SP_S + d4) = v;
    }

    // ---- Target scatter: per-component into swizzled st_t ----
    #pragma unroll
    for (int r = 0; r < 4; r++) {
        if (tidx[r] < 1008) {
            int e0 = tidx[r] << 2;
            float vv[4] = {tv[r].x, tv[r].y, tv[r].z, tv[r].w};
            #pragma unroll
            for (int c = 0; c < 4; c++) {
                int e = e0 + c;
                int q = e / 63;                 // magic-mul
                int d = e - q * 63;
                st_t[stoff(d, q)] = vv[c];
            }
        }
    }
    // d=63 pad row
    if (tid < NP) st_t[63 * 64 + tid] = 0.0f;
    __syncthreads();

    // ================= Norms from smem =================
    if (tid < NP) {
        const float4* ap = (const float4*)(sp + tid * SP_S);
        float s = 0.0f;
        #pragma unroll
        for (int k = 0; k < 16; k++) {
            float4 a = ap[k];
            s = fmaf(a.x, a.x, fmaf(a.y, a.y, fmaf(a.z, a.z, fmaf(a.w, a.w, s))));
        }
        pn[tid] = s;
    } else if (tid < 2 * NP) {
        const int q = tid - NP;
        float s = 0.0f;
        #pragma unroll 16
        for (int d = 0; d < 64; d++) {
            float b = st_t[stoff(d, q)];
            s = fmaf(b, b, s);
        }
        qn[q] = s;
    }
    __syncthreads();

    // ================= Mainloop: 4p x 4q, f32x2 along q =================
    const int tx = lane15;           // logical q-chunk
    const int ty = tid >> 4;
    const int q0 = tx * 4;
    const int p0 = ty * 4;

    u64 acc[4][2];
    #pragma unroll
    for (int i = 0; i < 4; i++) { acc[i][0] = 0ull; acc[i][1] = 0ull; }

    const float* a0 = sp + p0 * SP_S;

    #pragma unroll 4
    for (int dc = 0; dc < 64; dc += 4) {
        ulonglong2 b[4];
        #pragma unroll
        for (int d = 0; d < 4; d++) {
            const int dd = dc + d;
            b[d] = *(const ulonglong2*)(st_t + dd * 64 + ((tx ^ (dd & 15)) << 2));
        }
        #pragma unroll
        for (int i = 0; i < 4; i++) {
            float4 av = *(const float4*)(a0 + i * SP_S + dc);
            float a[4] = {av.x, av.y, av.z, av.w};
            #pragma unroll
            for (int d = 0; d < 4; d++) {
                u64 pa;
                asm("mov.b64 %0, {%1, %1};" : "=l"(pa) : "f"(a[d]));
                ffma2(acc[i][0], pa, b[d].x);
                ffma2(acc[i][1], pa, b[d].y);
            }
        }
    }

    // ================= Epilogue =================
    float pnr[4], ci2[4], qnr[4];
    #pragma unroll
    for (int i = 0; i < 4; i++) { pnr[i] = pn[p0 + i]; ci2[i] = cinv2[p0 + i]; }
    #pragma unroll
    for (int j = 0; j < 4; j++) qnr[j] = qn[q0 + j];

    float cmin[4] = {1e30f, 1e30f, 1e30f, 1e30f};
    float rmin[4];
    #pragma unroll
    for (int i = 0; i < 4; i++) {
        float dot[4];
        unpack2(dot[0], dot[1], acc[i][0]);
        unpack2(dot[2], dot[3], acc[i][1]);
        float rmn = 1e30f;
        #pragma unroll
        for (int j = 0; j < 4; j++) {
            float d2 = fmaxf(fmaf(-2.0f, dot[j], pnr[i] + qnr[j]), 0.0f);
            rmn = fminf(rmn, d2);
            cmin[j] = fminf(cmin[j], d2 * ci2[i]);
        }
        rmin[i] = rmn;
    }

    // row mins over tx lanes (bits 0..3)
    #pragma unroll
    for (int m = 1; m < 16; m <<= 1) {
        #pragma unroll
        for (int i = 0; i < 4; i++)
            rmin[i] = fminf(rmin[i], __shfl_xor_sync(0xFFFFFFFFu, rmin[i], m));
    }
    if (lane15 == 0) {
        #pragma unroll
        for (int i = 0; i < 4; i++) rm[p0 + i] = rmin[i];
    }
    // col mins: fold the two ty's per warp, then across warps via cm
    #pragma unroll
    for (int j = 0; j < 4; j++)
        cmin[j] = fminf(cmin[j], __shfl_xor_sync(0xFFFFFFFFu, cmin[j], 16));
    if ((tid & 31) < 16) {
        const int w = tid >> 5;
        #pragma unroll
        for (int j = 0; j < 4; j++) cm[w * CM_S + q0 + j] = cmin[j];
    }
    __syncthreads();

    // ================= Final: 128 sqrts + block sum =================
    float val = 0.0f;
    if (tid < NP) {
        val = conf[tid] * sqrtf(rm[tid]);
    } else if (tid < 2 * NP) {
        int q = tid - NP;
        float m = cm[q];
        #pragma unroll
        for (int u = 1; u < 8; u++) m = fminf(m, cm[u * CM_S + q]);
        val = sqrtf(m);
    }

    if (tid < 128) red[tid] = val;
    __syncthreads();
    if (tid < 64) red[tid] += red[tid + 64];
    __syncthreads();
    if (tid < 32) {
        float s = red[tid] + red[tid + 32];
        #pragma unroll
        for (int off = 16; off > 0; off >>= 1)
            s += __shfl_down_sync(0xFFFFFFFFu, s, off);
        if (tid == 0) out[bs] = s;
    }
}

extern "C" void kernel_launch(void* const* d_in, const int* in_sizes, int n_in,
                              void* d_out, int out_size)
{
    const float* inp = (const float*)d_in[0];
    const float* tgt = (const float*)d_in[1];
    float* out = (float*)d_out;
    cross_mse_loss_kernel<<<1024, 256>>>(inp, tgt, out);
}